// round 4
// baseline (speedup 1.0000x reference)
#include <cuda_runtime.h>
#include <math.h>
#include <stdint.h>

#define N_NODES 50000
#define N_EDGES 600000
#define IN_DIM  384
#define HID     128
#define HYP     256
#define EPSV    1e-10f
#define LATB    143
#define NPB     352          // 143*352 = 50336 >= 50000

// ---------------- scratch ----------------
__device__ float g_xemb[N_NODES * HID];
__device__ float g_acc [N_NODES * HID];
__device__ float g_curA[N_NODES * HID];
__device__ float g_curB[N_NODES * HID];
__device__ float g_Hm  [N_NODES * HYP];
__device__ float g_lat [HYP * HID];
__device__ float g_latP[LATB * HYP * HID];
__device__ float g_dinv[N_NODES];
__device__ int2  g_csr2[N_EDGES];
__device__ int   g_deg [N_NODES];
__device__ int   g_rowptr[N_NODES + 1];
__device__ int   g_fill[N_NODES];
__device__ int   g_part[64];

// ---------------- tf32 mma helpers ----------------
__device__ __forceinline__ uint32_t tf32c(float f) {
    uint32_t r;
    asm("cvt.rna.tf32.f32 %0, %1;" : "=r"(r) : "f"(f));
    return r;
}

__device__ __forceinline__ void mma8(float* c,
                                     uint32_t a0, uint32_t a1, uint32_t a2, uint32_t a3,
                                     uint32_t b0, uint32_t b1) {
    asm volatile(
        "mma.sync.aligned.m16n8k8.row.col.f32.tf32.tf32.f32 "
        "{%0,%1,%2,%3},{%4,%5,%6,%7},{%8,%9},{%0,%1,%2,%3};"
        : "+f"(c[0]), "+f"(c[1]), "+f"(c[2]), "+f"(c[3])
        : "r"(a0), "r"(a1), "r"(a2), "r"(a3), "r"(b0), "r"(b1));
}

// B pair packing: element (k = ks*8+p, n) slot0 and (k = ks*8+p+4, n) slot1
// index = ks*(N*8) + (n*4 + p)*2 + slot   (u32 units)
__device__ __forceinline__ int bpk_idx(int N8, int row, int n) {
    int ks = row >> 3, rr = row & 7;
    return ks * N8 + (n * 4 + (rr & 3)) * 2 + (rr >> 2);
}

// ---------------- setup kernels ----------------
__global__ void k_zero() {
    int i = blockIdx.x * blockDim.x + threadIdx.x;
    if (i < N_NODES) { g_deg[i] = 0; g_fill[i] = 0; }
}

__global__ void k_deg(const int* __restrict__ dst) {
    int e = blockIdx.x * blockDim.x + threadIdx.x;
    if (e < N_EDGES) atomicAdd(&g_deg[dst[e]], 1);
}

__global__ void k_scan1() {
    __shared__ int sh[1024];
    int i = blockIdx.x * 1024 + threadIdx.x;
    int v = (i < N_NODES) ? g_deg[i] : 0;
    sh[threadIdx.x] = v;
    __syncthreads();
    for (int off = 1; off < 1024; off <<= 1) {
        int t = (threadIdx.x >= off) ? sh[threadIdx.x - off] : 0;
        __syncthreads();
        sh[threadIdx.x] += t;
        __syncthreads();
    }
    if (i < N_NODES) g_rowptr[i] = sh[threadIdx.x] - v;
    if (threadIdx.x == 1023) g_part[blockIdx.x] = sh[1023];
}

__global__ void k_scan2(int nb) {
    __shared__ int sh[64];
    int v = (threadIdx.x < nb) ? g_part[threadIdx.x] : 0;
    sh[threadIdx.x] = v;
    __syncthreads();
    for (int off = 1; off < 64; off <<= 1) {
        int t = (threadIdx.x >= off) ? sh[threadIdx.x - off] : 0;
        __syncthreads();
        sh[threadIdx.x] += t;
        __syncthreads();
    }
    if (threadIdx.x < nb) g_part[threadIdx.x] = sh[threadIdx.x] - v;
}

__global__ void k_scan3() {
    int i = blockIdx.x * 1024 + threadIdx.x;
    if (i < N_NODES) g_rowptr[i] += g_part[blockIdx.x];
}

__global__ void k_dinv() {
    int i = blockIdx.x * blockDim.x + threadIdx.x;
    if (i == 0) g_rowptr[N_NODES] = N_EDGES;
    if (i < N_NODES) {
        int d = g_deg[i];
        g_dinv[i] = (d > 0) ? rsqrtf((float)d) : 0.f;
    }
}

__global__ void k_fill(const int* __restrict__ src, const int* __restrict__ dst) {
    int e = blockIdx.x * blockDim.x + threadIdx.x;
    if (e < N_EDGES) {
        int d = dst[e], s = src[e];
        int pos = g_rowptr[d] + atomicAdd(&g_fill[d], 1);
        g_csr2[pos] = make_int2(s, __float_as_int(g_dinv[s] * g_dinv[d]));
    }
}

// ---------------- G1: x_emb = x @ w_feat + b_feat ; acc = x_emb ----------------
__global__ __launch_bounds__(256) void k_gemm1(const float* __restrict__ x,
                                               const float* __restrict__ w,
                                               const float* __restrict__ b) {
    __shared__ uint32_t As[128 * 20];
    __shared__ uint32_t Bs2[2048];            // 16 x 128
    int t = threadIdx.x, lane = t & 31, wid = t >> 5;
    int g = lane >> 2, t4 = lane & 3;
    int r0 = blockIdx.x * 128, m0 = wid * 16;
    float acc[16][4];
#pragma unroll
    for (int n = 0; n < 16; n++) { acc[n][0] = acc[n][1] = acc[n][2] = acc[n][3] = 0.f; }

    for (int k0 = 0; k0 < IN_DIM; k0 += 16) {
        for (int i = t; i < 512; i += 256) {
            int row = i >> 2, c4 = (i & 3) * 4;
            int gr = min(r0 + row, N_NODES - 1);
            float4 v = *(const float4*)(x + (size_t)gr * IN_DIM + k0 + c4);
            uint32_t* ap = &As[row * 20 + c4];
            ap[0] = tf32c(v.x); ap[1] = tf32c(v.y); ap[2] = tf32c(v.z); ap[3] = tf32c(v.w);
        }
        for (int i = t; i < 512; i += 256) {
            int row = i >> 5, c4 = (i & 31) * 4;
            float4 v = *(const float4*)(w + (k0 + row) * HID + c4);
            Bs2[bpk_idx(1024, row, c4 + 0)] = tf32c(v.x);
            Bs2[bpk_idx(1024, row, c4 + 1)] = tf32c(v.y);
            Bs2[bpk_idx(1024, row, c4 + 2)] = tf32c(v.z);
            Bs2[bpk_idx(1024, row, c4 + 3)] = tf32c(v.w);
        }
        __syncthreads();
#pragma unroll
        for (int ks = 0; ks < 2; ks++) {
            int ar = (m0 + g) * 20 + ks * 8 + t4;
            uint32_t a0 = As[ar], a1 = As[ar + 160], a2 = As[ar + 4], a3 = As[ar + 164];
            const uint32_t* bp = &Bs2[ks * 1024 + t4 * 2];
#pragma unroll
            for (int nt = 0; nt < 16; nt++) {
                uint2 bv = *(const uint2*)&bp[(nt * 8 + g) * 8];
                mma8(acc[nt], a0, a1, a2, a3, bv.x, bv.y);
            }
        }
        __syncthreads();
    }
    int rA = r0 + m0 + g, rB = rA + 8;
#pragma unroll
    for (int nt = 0; nt < 16; nt++) {
        int cn = nt * 8 + t4 * 2;
        float b0 = b[cn], b1 = b[cn + 1];
        if (rA < N_NODES) {
            float2 v = make_float2(acc[nt][0] + b0, acc[nt][1] + b1);
            *(float2*)&g_xemb[rA * HID + cn] = v;
            *(float2*)&g_acc [rA * HID + cn] = v;
        }
        if (rB < N_NODES) {
            float2 v = make_float2(acc[nt][2] + b0, acc[nt][3] + b1);
            *(float2*)&g_xemb[rB * HID + cn] = v;
            *(float2*)&g_acc [rB * HID + cn] = v;
        }
    }
}

// ---------------- propagation: warp per node, float4 ----------------
__global__ __launch_bounds__(128) void k_prop(int step) {
    const float* cur = (step == 0) ? g_xemb : ((step == 1) ? g_curA : g_curB);
    float*       nxt = (step == 0) ? g_curA : ((step == 1) ? g_curB : g_curA);
    int d = blockIdx.x * 4 + (threadIdx.x >> 5);
    if (d >= N_NODES) return;
    int lane = threadIdx.x & 31;
    int s0 = g_rowptr[d], s1 = g_rowptr[d + 1];
    float4 sum = make_float4(0.f, 0.f, 0.f, 0.f);
    for (int j = s0; j < s1; j++) {
        int2 e = g_csr2[j];
        float v = __int_as_float(e.y);
        float4 c4v = *(const float4*)&cur[(size_t)e.x * HID + lane * 4];
        sum.x = fmaf(c4v.x, v, sum.x);
        sum.y = fmaf(c4v.y, v, sum.y);
        sum.z = fmaf(c4v.z, v, sum.z);
        sum.w = fmaf(c4v.w, v, sum.w);
    }
    size_t o = (size_t)d * HID + lane * 4;
    *(float4*)&nxt[o] = sum;
    float4 a = *(const float4*)&g_acc[o];
    a.x += sum.x; a.y += sum.y; a.z += sum.z; a.w += sum.w;
    *(float4*)&g_acc[o] = a;
}

// ---------------- Hm = softmax((x_emb @ w_hyper + gumbel)*2) ----------------
__global__ __launch_bounds__(256) void k_hyp(const float* __restrict__ wh,
                                             const float* __restrict__ u) {
    __shared__ uint32_t As[128 * 20];
    __shared__ uint32_t Bs2[4096];            // 16 x 256
    int t = threadIdx.x, lane = t & 31, wid = t >> 5;
    int g = lane >> 2, t4 = lane & 3;
    int r0 = blockIdx.x * 128, m0 = wid * 16;
    float acc[32][4];
#pragma unroll
    for (int n = 0; n < 32; n++) { acc[n][0] = acc[n][1] = acc[n][2] = acc[n][3] = 0.f; }

    for (int k0 = 0; k0 < HID; k0 += 16) {
        for (int i = t; i < 512; i += 256) {
            int row = i >> 2, c4 = (i & 3) * 4;
            int gr = min(r0 + row, N_NODES - 1);
            float4 v = *(const float4*)(g_xemb + (size_t)gr * HID + k0 + c4);
            uint32_t* ap = &As[row * 20 + c4];
            ap[0] = tf32c(v.x); ap[1] = tf32c(v.y); ap[2] = tf32c(v.z); ap[3] = tf32c(v.w);
        }
        for (int i = t; i < 1024; i += 256) {
            int row = i >> 6, c4 = (i & 63) * 4;
            float4 v = *(const float4*)(wh + (k0 + row) * HYP + c4);
            Bs2[bpk_idx(2048, row, c4 + 0)] = tf32c(v.x);
            Bs2[bpk_idx(2048, row, c4 + 1)] = tf32c(v.y);
            Bs2[bpk_idx(2048, row, c4 + 2)] = tf32c(v.z);
            Bs2[bpk_idx(2048, row, c4 + 3)] = tf32c(v.w);
        }
        __syncthreads();
#pragma unroll
        for (int ks = 0; ks < 2; ks++) {
            int ar = (m0 + g) * 20 + ks * 8 + t4;
            uint32_t a0 = As[ar], a1 = As[ar + 160], a2 = As[ar + 4], a3 = As[ar + 164];
            const uint32_t* bp = &Bs2[ks * 2048 + t4 * 2];
#pragma unroll
            for (int nt = 0; nt < 32; nt++) {
                uint2 bv = *(const uint2*)&bp[(nt * 8 + g) * 8];
                mma8(acc[nt], a0, a1, a2, a3, bv.x, bv.y);
            }
        }
        __syncthreads();
    }

    int rA = r0 + m0 + g, rB = rA + 8;
    int uA = min(rA, N_NODES - 1), uB = min(rB, N_NODES - 1);
    float mA = -1e30f, mB = -1e30f;
#pragma unroll
    for (int nt = 0; nt < 32; nt++) {
        int cn = nt * 8 + t4 * 2;
        float2 ua = *(const float2*)(u + (size_t)uA * HYP + cn);
        float2 ub = *(const float2*)(u + (size_t)uB * HYP + cn);
        // inner log precise (relative accuracy matters near u->1), outer fast
        acc[nt][0] = (acc[nt][0] - __logf(-logf(ua.x + EPSV) + EPSV)) * 2.f;
        acc[nt][1] = (acc[nt][1] - __logf(-logf(ua.y + EPSV) + EPSV)) * 2.f;
        acc[nt][2] = (acc[nt][2] - __logf(-logf(ub.x + EPSV) + EPSV)) * 2.f;
        acc[nt][3] = (acc[nt][3] - __logf(-logf(ub.y + EPSV) + EPSV)) * 2.f;
        mA = fmaxf(mA, fmaxf(acc[nt][0], acc[nt][1]));
        mB = fmaxf(mB, fmaxf(acc[nt][2], acc[nt][3]));
    }
    mA = fmaxf(mA, __shfl_xor_sync(0xffffffffu, mA, 1));
    mA = fmaxf(mA, __shfl_xor_sync(0xffffffffu, mA, 2));
    mB = fmaxf(mB, __shfl_xor_sync(0xffffffffu, mB, 1));
    mB = fmaxf(mB, __shfl_xor_sync(0xffffffffu, mB, 2));
    float sA = 0.f, sB = 0.f;
#pragma unroll
    for (int nt = 0; nt < 32; nt++) {
        acc[nt][0] = __expf(acc[nt][0] - mA);
        acc[nt][1] = __expf(acc[nt][1] - mA);
        acc[nt][2] = __expf(acc[nt][2] - mB);
        acc[nt][3] = __expf(acc[nt][3] - mB);
        sA += acc[nt][0] + acc[nt][1];
        sB += acc[nt][2] + acc[nt][3];
    }
    sA += __shfl_xor_sync(0xffffffffu, sA, 1);
    sA += __shfl_xor_sync(0xffffffffu, sA, 2);
    sB += __shfl_xor_sync(0xffffffffu, sB, 1);
    sB += __shfl_xor_sync(0xffffffffu, sB, 2);
    float iA = 1.f / sA, iB = 1.f / sB;
#pragma unroll
    for (int nt = 0; nt < 32; nt++) {
        int cn = nt * 8 + t4 * 2;
        if (rA < N_NODES)
            *(float2*)&g_Hm[(size_t)rA * HYP + cn] = make_float2(acc[nt][0] * iA, acc[nt][1] * iA);
        if (rB < N_NODES)
            *(float2*)&g_Hm[(size_t)rB * HYP + cn] = make_float2(acc[nt][2] * iB, acc[nt][3] * iB);
    }
}

// ---------------- lat partials: latP[b] = Hm[rows_b]^T @ xemb[rows_b] ----------------
__global__ __launch_bounds__(512) void k_lat() {
    __shared__ uint32_t Hs2[4096];            // 16 nodes x 256 h, pair-packed
    __shared__ uint32_t Xs2[2048];            // 16 nodes x 128 c, pair-packed
    int t = threadIdx.x, lane = t & 31, wid = t >> 5;
    int g = lane >> 2, t4 = lane & 3;
    int h0 = wid * 16;
    int base = blockIdx.x * NPB;
    float acc[16][4];
#pragma unroll
    for (int n = 0; n < 16; n++) { acc[n][0] = acc[n][1] = acc[n][2] = acc[n][3] = 0.f; }

    for (int c = 0; c < NPB; c += 16) {
        for (int i = t; i < 1024; i += 512) {
            int row = i >> 6, c4 = (i & 63) * 4;
            int node = base + c + row;
            float4 v = (node < N_NODES) ? *(const float4*)&g_Hm[(size_t)node * HYP + c4]
                                        : make_float4(0.f, 0.f, 0.f, 0.f);
            Hs2[bpk_idx(2048, row, c4 + 0)] = tf32c(v.x);
            Hs2[bpk_idx(2048, row, c4 + 1)] = tf32c(v.y);
            Hs2[bpk_idx(2048, row, c4 + 2)] = tf32c(v.z);
            Hs2[bpk_idx(2048, row, c4 + 3)] = tf32c(v.w);
        }
        {
            int i = t;
            int row = i >> 5, c4 = (i & 31) * 4;
            int node = base + c + row;
            float4 v = (node < N_NODES) ? *(const float4*)&g_xemb[(size_t)node * HID + c4]
                                        : make_float4(0.f, 0.f, 0.f, 0.f);
            Xs2[bpk_idx(1024, row, c4 + 0)] = tf32c(v.x);
            Xs2[bpk_idx(1024, row, c4 + 1)] = tf32c(v.y);
            Xs2[bpk_idx(1024, row, c4 + 2)] = tf32c(v.z);
            Xs2[bpk_idx(1024, row, c4 + 3)] = tf32c(v.w);
        }
        __syncthreads();
#pragma unroll
        for (int ks = 0; ks < 2; ks++) {
            const uint32_t* hp = &Hs2[ks * 2048 + t4 * 2];
            uint2 av1 = *(const uint2*)&hp[(h0 + g) * 8];       // a0 (k=t4), a2 (k=t4+4)
            uint2 av2 = *(const uint2*)&hp[(h0 + g + 8) * 8];   // a1, a3
            const uint32_t* bp = &Xs2[ks * 1024 + t4 * 2];
#pragma unroll
            for (int nt = 0; nt < 16; nt++) {
                uint2 bv = *(const uint2*)&bp[(nt * 8 + g) * 8];
                mma8(acc[nt], av1.x, av2.x, av1.y, av2.y, bv.x, bv.y);
            }
        }
        __syncthreads();
    }
    float* pb = &g_latP[(size_t)blockIdx.x * HYP * HID];
#pragma unroll
    for (int nt = 0; nt < 16; nt++) {
        int cn = nt * 8 + t4 * 2;
        *(float2*)&pb[(h0 + g) * HID + cn]     = make_float2(acc[nt][0], acc[nt][1]);
        *(float2*)&pb[(h0 + g + 8) * HID + cn] = make_float2(acc[nt][2], acc[nt][3]);
    }
}

__global__ void k_latred() {
    int i = blockIdx.x * blockDim.x + threadIdx.x;
    if (i < HYP * HID) {
        float s = 0.f;
        for (int b = 0; b < LATB; b++) s += g_latP[(size_t)b * HYP * HID + i];
        g_lat[i] = s;
    }
}

// ---------------- final = acc/4 + 0.1*normalize(Hm @ lat) ----------------
__global__ __launch_bounds__(256) void k_final(float* __restrict__ outF) {
    __shared__ uint32_t As[128 * 20];
    __shared__ uint32_t Bs2[2048];
    int t = threadIdx.x, lane = t & 31, wid = t >> 5;
    int g = lane >> 2, t4 = lane & 3;
    int r0 = blockIdx.x * 128, m0 = wid * 16;
    float acc[16][4];
#pragma unroll
    for (int n = 0; n < 16; n++) { acc[n][0] = acc[n][1] = acc[n][2] = acc[n][3] = 0.f; }

    for (int k0 = 0; k0 < HYP; k0 += 16) {
        for (int i = t; i < 512; i += 256) {
            int row = i >> 2, c4 = (i & 3) * 4;
            int gr = min(r0 + row, N_NODES - 1);
            float4 v = *(const float4*)(g_Hm + (size_t)gr * HYP + k0 + c4);
            uint32_t* ap = &As[row * 20 + c4];
            ap[0] = tf32c(v.x); ap[1] = tf32c(v.y); ap[2] = tf32c(v.z); ap[3] = tf32c(v.w);
        }
        for (int i = t; i < 512; i += 256) {
            int row = i >> 5, c4 = (i & 31) * 4;
            float4 v = *(const float4*)(g_lat + (k0 + row) * HID + c4);
            Bs2[bpk_idx(1024, row, c4 + 0)] = tf32c(v.x);
            Bs2[bpk_idx(1024, row, c4 + 1)] = tf32c(v.y);
            Bs2[bpk_idx(1024, row, c4 + 2)] = tf32c(v.z);
            Bs2[bpk_idx(1024, row, c4 + 3)] = tf32c(v.w);
        }
        __syncthreads();
#pragma unroll
        for (int ks = 0; ks < 2; ks++) {
            int ar = (m0 + g) * 20 + ks * 8 + t4;
            uint32_t a0 = As[ar], a1 = As[ar + 160], a2 = As[ar + 4], a3 = As[ar + 164];
            const uint32_t* bp = &Bs2[ks * 1024 + t4 * 2];
#pragma unroll
            for (int nt = 0; nt < 16; nt++) {
                uint2 bv = *(const uint2*)&bp[(nt * 8 + g) * 8];
                mma8(acc[nt], a0, a1, a2, a3, bv.x, bv.y);
            }
        }
        __syncthreads();
    }

    float ssA = 0.f, ssB = 0.f;
#pragma unroll
    for (int nt = 0; nt < 16; nt++) {
        ssA += acc[nt][0] * acc[nt][0] + acc[nt][1] * acc[nt][1];
        ssB += acc[nt][2] * acc[nt][2] + acc[nt][3] * acc[nt][3];
    }
    ssA += __shfl_xor_sync(0xffffffffu, ssA, 1);
    ssA += __shfl_xor_sync(0xffffffffu, ssA, 2);
    ssB += __shfl_xor_sync(0xffffffffu, ssB, 1);
    ssB += __shfl_xor_sync(0xffffffffu, ssB, 2);
    float iA = 0.1f / fmaxf(sqrtf(ssA), 1e-12f);
    float iB = 0.1f / fmaxf(sqrtf(ssB), 1e-12f);
    int rA = r0 + m0 + g, rB = rA + 8;
#pragma unroll
    for (int nt = 0; nt < 16; nt++) {
        int cn = nt * 8 + t4 * 2;
        if (rA < N_NODES) {
            float2 ag = *(const float2*)&g_acc[rA * HID + cn];
            *(float2*)&outF[(size_t)rA * HID + cn] =
                make_float2(ag.x * 0.25f + acc[nt][0] * iA, ag.y * 0.25f + acc[nt][1] * iA);
        }
        if (rB < N_NODES) {
            float2 ag = *(const float2*)&g_acc[rB * HID + cn];
            *(float2*)&outF[(size_t)rB * HID + cn] =
                make_float2(ag.x * 0.25f + acc[nt][2] * iB, ag.y * 0.25f + acc[nt][3] * iB);
        }
    }
}

// ---------------- vis/txt = relu(final @ [wv|wt] + [bv|bt]) ----------------
__global__ __launch_bounds__(256) void k_out(const float* __restrict__ fin,
                                             const float* __restrict__ wv, const float* __restrict__ bv,
                                             const float* __restrict__ wt, const float* __restrict__ bt,
                                             float* __restrict__ vis, float* __restrict__ txt) {
    __shared__ uint32_t As[64 * 20];
    __shared__ uint32_t Bs2[4096];
    int t = threadIdx.x, lane = t & 31, wid = t >> 5;
    int g = lane >> 2, t4 = lane & 3;
    int mt = wid & 3, half = wid >> 2;
    int r0 = blockIdx.x * 64, m0 = mt * 16;
    float acc[16][4];
#pragma unroll
    for (int n = 0; n < 16; n++) { acc[n][0] = acc[n][1] = acc[n][2] = acc[n][3] = 0.f; }

    for (int k0 = 0; k0 < HID; k0 += 16) {
        {
            int i = t;
            int row = i >> 2, c4 = (i & 3) * 4;
            int gr = min(r0 + row, N_NODES - 1);
            float4 v = *(const float4*)(fin + (size_t)gr * HID + k0 + c4);
            uint32_t* ap = &As[row * 20 + c4];
            ap[0] = tf32c(v.x); ap[1] = tf32c(v.y); ap[2] = tf32c(v.z); ap[3] = tf32c(v.w);
        }
        for (int i = t; i < 1024; i += 256) {
            int row = i >> 6, c4 = (i & 63) * 4;
            const float* srcp = (c4 < 128) ? (wv + (k0 + row) * HID + c4)
                                           : (wt + (k0 + row) * HID + (c4 - 128));
            float4 v = *(const float4*)srcp;
            Bs2[bpk_idx(2048, row, c4 + 0)] = tf32c(v.x);
            Bs2[bpk_idx(2048, row, c4 + 1)] = tf32c(v.y);
            Bs2[bpk_idx(2048, row, c4 + 2)] = tf32c(v.z);
            Bs2[bpk_idx(2048, row, c4 + 3)] = tf32c(v.w);
        }
        __syncthreads();
#pragma unroll
        for (int ks = 0; ks < 2; ks++) {
            int ar = (m0 + g) * 20 + ks * 8 + t4;
            uint32_t a0 = As[ar], a1 = As[ar + 160], a2 = As[ar + 4], a3 = As[ar + 164];
            const uint32_t* bp = &Bs2[ks * 2048 + half * 1024 + t4 * 2];
#pragma unroll
            for (int nt = 0; nt < 16; nt++) {
                uint2 bv = *(const uint2*)&bp[(nt * 8 + g) * 8];
                mma8(acc[nt], a0, a1, a2, a3, bv.x, bv.y);
            }
        }
        __syncthreads();
    }

    const float* bias = half ? bt : bv;
    float* o = half ? txt : vis;
    int rA = r0 + m0 + g, rB = rA + 8;
#pragma unroll
    for (int nt = 0; nt < 16; nt++) {
        int cn = nt * 8 + t4 * 2;
        float b0 = bias[cn], b1 = bias[cn + 1];
        if (rA < N_NODES)
            *(float2*)&o[(size_t)rA * HID + cn] =
                make_float2(fmaxf(acc[nt][0] + b0, 0.f), fmaxf(acc[nt][1] + b1, 0.f));
        if (rB < N_NODES)
            *(float2*)&o[(size_t)rB * HID + cn] =
                make_float2(fmaxf(acc[nt][2] + b0, 0.f), fmaxf(acc[nt][3] + b1, 0.f));
    }
}

// ---------------- launcher ----------------
extern "C" void kernel_launch(void* const* d_in, const int* in_sizes, int n_in,
                              void* d_out, int out_size) {
    const float* x       = (const float*)d_in[0];
    const int*   ei      = (const int*)  d_in[1];
    const float* u       = (const float*)d_in[2];
    const float* w_feat  = (const float*)d_in[3];
    const float* b_feat  = (const float*)d_in[4];
    const float* w_hyper = (const float*)d_in[5];
    const float* w_vis   = (const float*)d_in[6];
    const float* b_vis   = (const float*)d_in[7];
    const float* w_txt   = (const float*)d_in[8];
    const float* b_txt   = (const float*)d_in[9];

    float* out  = (float*)d_out;
    float* outF = out;
    float* outV = out + (size_t)N_NODES * HID;
    float* outT = out + (size_t)2 * N_NODES * HID;

    const int* src = ei;
    const int* dst = ei + N_EDGES;

    int nb = (N_NODES + 1023) / 1024;         // 49
    int g128 = (N_NODES + 127) / 128;         // 391
    int g64  = (N_NODES + 63) / 64;           // 782

    k_zero <<<(N_NODES + 255) / 256, 256>>>();
    k_deg  <<<(N_EDGES + 255) / 256, 256>>>(dst);
    k_scan1<<<nb, 1024>>>();
    k_scan2<<<1, 64>>>(nb);
    k_scan3<<<nb, 1024>>>();
    k_dinv <<<(N_NODES + 255) / 256, 256>>>();
    k_fill <<<(N_EDGES + 255) / 256, 256>>>(src, dst);

    k_gemm1<<<g128, 256>>>(x, w_feat, b_feat);

    k_prop<<<(N_NODES + 3) / 4, 128>>>(0);
    k_prop<<<(N_NODES + 3) / 4, 128>>>(1);
    k_prop<<<(N_NODES + 3) / 4, 128>>>(2);

    k_hyp<<<g128, 256>>>(w_hyper, u);

    k_lat<<<LATB, 512>>>();
    k_latred<<<(HYP * HID + 1023) / 1024, 1024>>>();

    k_final<<<g128, 256>>>(outF);
    k_out  <<<g64, 256>>>(outF, w_vis, b_vis, w_txt, b_txt, outV, outT);
}

// round 5
// speedup vs baseline: 1.5347x; 1.5347x over previous
#include <cuda_runtime.h>
#include <math.h>
#include <stdint.h>

#define N_NODES 50000
#define N_EDGES 600000
#define IN_DIM  384
#define HID     128
#define HYP     256
#define EPSV    1e-10f
#define LATB    143
#define NPB     352          // 143*352 = 50336 >= 50000

// ---------------- scratch ----------------
__device__ float g_xemb[N_NODES * HID];
__device__ float g_acc [N_NODES * HID];
__device__ float g_curA[N_NODES * HID];
__device__ float g_curB[N_NODES * HID];
__device__ float g_Hm  [N_NODES * HYP];
__device__ float g_lat [HYP * HID];
__device__ float g_latP[LATB * HYP * HID];
__device__ float g_dinv[N_NODES];
__device__ int2  g_csr2[N_EDGES];
__device__ int   g_deg [N_NODES];
__device__ int   g_rowptr[N_NODES + 1];
__device__ int   g_fill[N_NODES];
__device__ int   g_part[64];

// ---------------- tf32 mma helpers ----------------
__device__ __forceinline__ uint32_t tf32c(float f) {
    uint32_t r;
    asm("cvt.rna.tf32.f32 %0, %1;" : "=r"(r) : "f"(f));
    return r;
}

__device__ __forceinline__ uint4 tf32c4(float4 v) {
    uint4 r;
    r.x = tf32c(v.x); r.y = tf32c(v.y); r.z = tf32c(v.z); r.w = tf32c(v.w);
    return r;
}

__device__ __forceinline__ void mma8(float* c,
                                     uint32_t a0, uint32_t a1, uint32_t a2, uint32_t a3,
                                     uint32_t b0, uint32_t b1) {
    asm volatile(
        "mma.sync.aligned.m16n8k8.row.col.f32.tf32.tf32.f32 "
        "{%0,%1,%2,%3},{%4,%5,%6,%7},{%8,%9},{%0,%1,%2,%3};"
        : "+f"(c[0]), "+f"(c[1]), "+f"(c[2]), "+f"(c[3])
        : "r"(a0), "r"(a1), "r"(a2), "r"(a3), "r"(b0), "r"(b1));
}

// ---------------- setup kernels ----------------
__global__ void k_zero() {
    int i = blockIdx.x * blockDim.x + threadIdx.x;
    if (i < N_NODES) { g_deg[i] = 0; g_fill[i] = 0; }
}

__global__ void k_deg(const int* __restrict__ dst) {
    int e = blockIdx.x * blockDim.x + threadIdx.x;
    if (e < N_EDGES) atomicAdd(&g_deg[dst[e]], 1);
}

__global__ void k_scan1() {
    __shared__ int sh[1024];
    int i = blockIdx.x * 1024 + threadIdx.x;
    int v = (i < N_NODES) ? g_deg[i] : 0;
    sh[threadIdx.x] = v;
    __syncthreads();
    for (int off = 1; off < 1024; off <<= 1) {
        int t = (threadIdx.x >= off) ? sh[threadIdx.x - off] : 0;
        __syncthreads();
        sh[threadIdx.x] += t;
        __syncthreads();
    }
    if (i < N_NODES) g_rowptr[i] = sh[threadIdx.x] - v;
    if (threadIdx.x == 1023) g_part[blockIdx.x] = sh[1023];
}

__global__ void k_scan2(int nb) {
    __shared__ int sh[64];
    int v = (threadIdx.x < nb) ? g_part[threadIdx.x] : 0;
    sh[threadIdx.x] = v;
    __syncthreads();
    for (int off = 1; off < 64; off <<= 1) {
        int t = (threadIdx.x >= off) ? sh[threadIdx.x - off] : 0;
        __syncthreads();
        sh[threadIdx.x] += t;
        __syncthreads();
    }
    if (threadIdx.x < nb) g_part[threadIdx.x] = sh[threadIdx.x] - v;
}

__global__ void k_scan3() {
    int i = blockIdx.x * 1024 + threadIdx.x;
    if (i < N_NODES) g_rowptr[i] += g_part[blockIdx.x];
}

__global__ void k_dinv() {
    int i = blockIdx.x * blockDim.x + threadIdx.x;
    if (i == 0) g_rowptr[N_NODES] = N_EDGES;
    if (i < N_NODES) {
        int d = g_deg[i];
        g_dinv[i] = (d > 0) ? rsqrtf((float)d) : 0.f;
    }
}

__global__ void k_fill(const int* __restrict__ src, const int* __restrict__ dst) {
    int e = blockIdx.x * blockDim.x + threadIdx.x;
    if (e < N_EDGES) {
        int d = dst[e], s = src[e];
        int pos = g_rowptr[d] + atomicAdd(&g_fill[d], 1);
        g_csr2[pos] = make_int2(s, __float_as_int(g_dinv[s] * g_dinv[d]));
    }
}

// ---------------- G1: x_emb = x @ w_feat + b_feat ; acc = x_emb ----------------
// r3 layout; tf32 pre-converted at fill (uint4 STS.128), inner loop = LDS + HMMA only.
__global__ __launch_bounds__(256) void k_gemm1(const float* __restrict__ x,
                                               const float* __restrict__ w,
                                               const float* __restrict__ b) {
    __shared__ uint32_t As[128 * 20];
    __shared__ uint32_t Bs[16 * 136];
    int t = threadIdx.x, lane = t & 31, wid = t >> 5;
    int g = lane >> 2, t4 = lane & 3;
    int r0 = blockIdx.x * 128, m0 = wid * 16;
    float acc[16][4];
#pragma unroll
    for (int n = 0; n < 16; n++) { acc[n][0] = acc[n][1] = acc[n][2] = acc[n][3] = 0.f; }

    for (int k0 = 0; k0 < IN_DIM; k0 += 16) {
        for (int i = t; i < 512; i += 256) {
            int row = i >> 2, c4 = (i & 3) * 4;
            int gr = min(r0 + row, N_NODES - 1);
            *(uint4*)&As[row * 20 + c4] =
                tf32c4(*(const float4*)(x + (size_t)gr * IN_DIM + k0 + c4));
        }
        for (int i = t; i < 512; i += 256) {
            int row = i >> 5, c4 = (i & 31) * 4;
            *(uint4*)&Bs[row * 136 + c4] =
                tf32c4(*(const float4*)(w + (k0 + row) * HID + c4));
        }
        __syncthreads();
#pragma unroll
        for (int ks = 0; ks < 2; ks++) {
            int ar = (m0 + g) * 20 + ks * 8 + t4;
            uint32_t a0 = As[ar], a1 = As[ar + 160], a2 = As[ar + 4], a3 = As[ar + 164];
            const uint32_t* bp = &Bs[(ks * 8 + t4) * 136];
#pragma unroll
            for (int nt = 0; nt < 16; nt++)
                mma8(acc[nt], a0, a1, a2, a3, bp[nt * 8 + g], bp[544 + nt * 8 + g]);
        }
        __syncthreads();
    }
    int rA = r0 + m0 + g, rB = rA + 8;
#pragma unroll
    for (int nt = 0; nt < 16; nt++) {
        int cn = nt * 8 + t4 * 2;
        float b0 = b[cn], b1 = b[cn + 1];
        if (rA < N_NODES) {
            float2 v = make_float2(acc[nt][0] + b0, acc[nt][1] + b1);
            *(float2*)&g_xemb[rA * HID + cn] = v;
            *(float2*)&g_acc [rA * HID + cn] = v;
        }
        if (rB < N_NODES) {
            float2 v = make_float2(acc[nt][2] + b0, acc[nt][3] + b1);
            *(float2*)&g_xemb[rB * HID + cn] = v;
            *(float2*)&g_acc [rB * HID + cn] = v;
        }
    }
}

// ---------------- propagation: warp per node, float4 ----------------
__global__ __launch_bounds__(128) void k_prop(int step) {
    const float* cur = (step == 0) ? g_xemb : ((step == 1) ? g_curA : g_curB);
    float*       nxt = (step == 0) ? g_curA : ((step == 1) ? g_curB : g_curA);
    int d = blockIdx.x * 4 + (threadIdx.x >> 5);
    if (d >= N_NODES) return;
    int lane = threadIdx.x & 31;
    int s0 = g_rowptr[d], s1 = g_rowptr[d + 1];
    float4 sum = make_float4(0.f, 0.f, 0.f, 0.f);
    for (int j = s0; j < s1; j++) {
        int2 e = g_csr2[j];
        float v = __int_as_float(e.y);
        float4 c4v = *(const float4*)&cur[(size_t)e.x * HID + lane * 4];
        sum.x = fmaf(c4v.x, v, sum.x);
        sum.y = fmaf(c4v.y, v, sum.y);
        sum.z = fmaf(c4v.z, v, sum.z);
        sum.w = fmaf(c4v.w, v, sum.w);
    }
    size_t o = (size_t)d * HID + lane * 4;
    *(float4*)&nxt[o] = sum;
    float4 a = *(const float4*)&g_acc[o];
    a.x += sum.x; a.y += sum.y; a.z += sum.z; a.w += sum.w;
    *(float4*)&g_acc[o] = a;
}

// ---------------- Hm = softmax((x_emb @ w_hyper + gumbel)*2) ----------------
__global__ __launch_bounds__(256) void k_hyp(const float* __restrict__ wh,
                                             const float* __restrict__ u) {
    __shared__ uint32_t As[128 * 20];
    __shared__ uint32_t Bs[16 * 264];
    int t = threadIdx.x, lane = t & 31, wid = t >> 5;
    int g = lane >> 2, t4 = lane & 3;
    int r0 = blockIdx.x * 128, m0 = wid * 16;
    float acc[32][4];
#pragma unroll
    for (int n = 0; n < 32; n++) { acc[n][0] = acc[n][1] = acc[n][2] = acc[n][3] = 0.f; }

    for (int k0 = 0; k0 < HID; k0 += 16) {
        for (int i = t; i < 512; i += 256) {
            int row = i >> 2, c4 = (i & 3) * 4;
            int gr = min(r0 + row, N_NODES - 1);
            *(uint4*)&As[row * 20 + c4] =
                tf32c4(*(const float4*)(g_xemb + (size_t)gr * HID + k0 + c4));
        }
        for (int i = t; i < 1024; i += 256) {
            int row = i >> 6, c4 = (i & 63) * 4;
            *(uint4*)&Bs[row * 264 + c4] =
                tf32c4(*(const float4*)(wh + (k0 + row) * HYP + c4));
        }
        __syncthreads();
#pragma unroll
        for (int ks = 0; ks < 2; ks++) {
            int ar = (m0 + g) * 20 + ks * 8 + t4;
            uint32_t a0 = As[ar], a1 = As[ar + 160], a2 = As[ar + 4], a3 = As[ar + 164];
            const uint32_t* bp = &Bs[(ks * 8 + t4) * 264];
#pragma unroll
            for (int nt = 0; nt < 32; nt++)
                mma8(acc[nt], a0, a1, a2, a3, bp[nt * 8 + g], bp[1056 + nt * 8 + g]);
        }
        __syncthreads();
    }

    int rA = r0 + m0 + g, rB = rA + 8;
    int uA = min(rA, N_NODES - 1), uB = min(rB, N_NODES - 1);
    float mA = -1e30f, mB = -1e30f;
#pragma unroll
    for (int nt = 0; nt < 32; nt++) {
        int cn = nt * 8 + t4 * 2;
        float2 ua = *(const float2*)(u + (size_t)uA * HYP + cn);
        float2 ub = *(const float2*)(u + (size_t)uB * HYP + cn);
        // inner log precise (relative accuracy near u->1 matters), outer fast
        acc[nt][0] = (acc[nt][0] - __logf(-logf(ua.x + EPSV) + EPSV)) * 2.f;
        acc[nt][1] = (acc[nt][1] - __logf(-logf(ua.y + EPSV) + EPSV)) * 2.f;
        acc[nt][2] = (acc[nt][2] - __logf(-logf(ub.x + EPSV) + EPSV)) * 2.f;
        acc[nt][3] = (acc[nt][3] - __logf(-logf(ub.y + EPSV) + EPSV)) * 2.f;
        mA = fmaxf(mA, fmaxf(acc[nt][0], acc[nt][1]));
        mB = fmaxf(mB, fmaxf(acc[nt][2], acc[nt][3]));
    }
    mA = fmaxf(mA, __shfl_xor_sync(0xffffffffu, mA, 1));
    mA = fmaxf(mA, __shfl_xor_sync(0xffffffffu, mA, 2));
    mB = fmaxf(mB, __shfl_xor_sync(0xffffffffu, mB, 1));
    mB = fmaxf(mB, __shfl_xor_sync(0xffffffffu, mB, 2));
    float sA = 0.f, sB = 0.f;
#pragma unroll
    for (int nt = 0; nt < 32; nt++) {
        acc[nt][0] = __expf(acc[nt][0] - mA);
        acc[nt][1] = __expf(acc[nt][1] - mA);
        acc[nt][2] = __expf(acc[nt][2] - mB);
        acc[nt][3] = __expf(acc[nt][3] - mB);
        sA += acc[nt][0] + acc[nt][1];
        sB += acc[nt][2] + acc[nt][3];
    }
    sA += __shfl_xor_sync(0xffffffffu, sA, 1);
    sA += __shfl_xor_sync(0xffffffffu, sA, 2);
    sB += __shfl_xor_sync(0xffffffffu, sB, 1);
    sB += __shfl_xor_sync(0xffffffffu, sB, 2);
    float iA = 1.f / sA, iB = 1.f / sB;
#pragma unroll
    for (int nt = 0; nt < 32; nt++) {
        int cn = nt * 8 + t4 * 2;
        if (rA < N_NODES)
            *(float2*)&g_Hm[(size_t)rA * HYP + cn] = make_float2(acc[nt][0] * iA, acc[nt][1] * iA);
        if (rB < N_NODES)
            *(float2*)&g_Hm[(size_t)rB * HYP + cn] = make_float2(acc[nt][2] * iB, acc[nt][3] * iB);
    }
}

// ---------------- lat partials: latP[b] = Hm[rows_b]^T @ xemb[rows_b] ----------------
__global__ __launch_bounds__(512) void k_lat() {
    __shared__ uint32_t Hs[16 * 264];
    __shared__ uint32_t Xs[16 * 136];
    int t = threadIdx.x, lane = t & 31, wid = t >> 5;
    int g = lane >> 2, t4 = lane & 3;
    int h0 = wid * 16;
    int base = blockIdx.x * NPB;
    float acc[16][4];
#pragma unroll
    for (int n = 0; n < 16; n++) { acc[n][0] = acc[n][1] = acc[n][2] = acc[n][3] = 0.f; }

    for (int c = 0; c < NPB; c += 16) {
        for (int i = t; i < 1024; i += 512) {
            int row = i >> 6, c4 = (i & 63) * 4;
            int node = base + c + row;
            float4 v = (node < N_NODES) ? *(const float4*)&g_Hm[(size_t)node * HYP + c4]
                                        : make_float4(0.f, 0.f, 0.f, 0.f);
            *(uint4*)&Hs[row * 264 + c4] = tf32c4(v);
        }
        {
            int i = t;
            int row = i >> 5, c4 = (i & 31) * 4;
            int node = base + c + row;
            float4 v = (node < N_NODES) ? *(const float4*)&g_xemb[(size_t)node * HID + c4]
                                        : make_float4(0.f, 0.f, 0.f, 0.f);
            *(uint4*)&Xs[row * 136 + c4] = tf32c4(v);
        }
        __syncthreads();
#pragma unroll
        for (int ks = 0; ks < 2; ks++) {
            const uint32_t* hp  = &Hs[(ks * 8 + t4) * 264];
            const uint32_t* hp4 = hp + 4 * 264;
            uint32_t a0 = hp[h0 + g],  a1 = hp[h0 + g + 8];
            uint32_t a2 = hp4[h0 + g], a3 = hp4[h0 + g + 8];
            const uint32_t* bp = &Xs[(ks * 8 + t4) * 136];
#pragma unroll
            for (int nt = 0; nt < 16; nt++)
                mma8(acc[nt], a0, a1, a2, a3, bp[nt * 8 + g], bp[544 + nt * 8 + g]);
        }
        __syncthreads();
    }
    float* pb = &g_latP[(size_t)blockIdx.x * HYP * HID];
#pragma unroll
    for (int nt = 0; nt < 16; nt++) {
        int cn = nt * 8 + t4 * 2;
        *(float2*)&pb[(h0 + g) * HID + cn]     = make_float2(acc[nt][0], acc[nt][1]);
        *(float2*)&pb[(h0 + g + 8) * HID + cn] = make_float2(acc[nt][2], acc[nt][3]);
    }
}

__global__ void k_latred() {
    int i = blockIdx.x * blockDim.x + threadIdx.x;
    if (i < HYP * HID) {
        float s = 0.f;
        for (int b = 0; b < LATB; b++) s += g_latP[(size_t)b * HYP * HID + i];
        g_lat[i] = s;
    }
}

// ---------------- final = acc/4 + 0.1*normalize(Hm @ lat) ----------------
__global__ __launch_bounds__(256) void k_final(float* __restrict__ outF) {
    __shared__ uint32_t As[128 * 20];
    __shared__ uint32_t Bs[16 * 136];
    int t = threadIdx.x, lane = t & 31, wid = t >> 5;
    int g = lane >> 2, t4 = lane & 3;
    int r0 = blockIdx.x * 128, m0 = wid * 16;
    float acc[16][4];
#pragma unroll
    for (int n = 0; n < 16; n++) { acc[n][0] = acc[n][1] = acc[n][2] = acc[n][3] = 0.f; }

    for (int k0 = 0; k0 < HYP; k0 += 16) {
        for (int i = t; i < 512; i += 256) {
            int row = i >> 2, c4 = (i & 3) * 4;
            int gr = min(r0 + row, N_NODES - 1);
            *(uint4*)&As[row * 20 + c4] =
                tf32c4(*(const float4*)(g_Hm + (size_t)gr * HYP + k0 + c4));
        }
        for (int i = t; i < 512; i += 256) {
            int row = i >> 5, c4 = (i & 31) * 4;
            *(uint4*)&Bs[row * 136 + c4] =
                tf32c4(*(const float4*)(g_lat + (k0 + row) * HID + c4));
        }
        __syncthreads();
#pragma unroll
        for (int ks = 0; ks < 2; ks++) {
            int ar = (m0 + g) * 20 + ks * 8 + t4;
            uint32_t a0 = As[ar], a1 = As[ar + 160], a2 = As[ar + 4], a3 = As[ar + 164];
            const uint32_t* bp = &Bs[(ks * 8 + t4) * 136];
#pragma unroll
            for (int nt = 0; nt < 16; nt++)
                mma8(acc[nt], a0, a1, a2, a3, bp[nt * 8 + g], bp[544 + nt * 8 + g]);
        }
        __syncthreads();
    }

    float ssA = 0.f, ssB = 0.f;
#pragma unroll
    for (int nt = 0; nt < 16; nt++) {
        ssA += acc[nt][0] * acc[nt][0] + acc[nt][1] * acc[nt][1];
        ssB += acc[nt][2] * acc[nt][2] + acc[nt][3] * acc[nt][3];
    }
    ssA += __shfl_xor_sync(0xffffffffu, ssA, 1);
    ssA += __shfl_xor_sync(0xffffffffu, ssA, 2);
    ssB += __shfl_xor_sync(0xffffffffu, ssB, 1);
    ssB += __shfl_xor_sync(0xffffffffu, ssB, 2);
    float iA = 0.1f / fmaxf(sqrtf(ssA), 1e-12f);
    float iB = 0.1f / fmaxf(sqrtf(ssB), 1e-12f);
    int rA = r0 + m0 + g, rB = rA + 8;
#pragma unroll
    for (int nt = 0; nt < 16; nt++) {
        int cn = nt * 8 + t4 * 2;
        if (rA < N_NODES) {
            float2 ag = *(const float2*)&g_acc[rA * HID + cn];
            *(float2*)&outF[(size_t)rA * HID + cn] =
                make_float2(ag.x * 0.25f + acc[nt][0] * iA, ag.y * 0.25f + acc[nt][1] * iA);
        }
        if (rB < N_NODES) {
            float2 ag = *(const float2*)&g_acc[rB * HID + cn];
            *(float2*)&outF[(size_t)rB * HID + cn] =
                make_float2(ag.x * 0.25f + acc[nt][2] * iB, ag.y * 0.25f + acc[nt][3] * iB);
        }
    }
}

// ---------------- vis/txt = relu(final @ [wv|wt] + [bv|bt]) ----------------
__global__ __launch_bounds__(256) void k_out(const float* __restrict__ fin,
                                             const float* __restrict__ wv, const float* __restrict__ bv,
                                             const float* __restrict__ wt, const float* __restrict__ bt,
                                             float* __restrict__ vis, float* __restrict__ txt) {
    __shared__ uint32_t As[64 * 20];
    __shared__ uint32_t Bs[16 * 264];
    int t = threadIdx.x, lane = t & 31, wid = t >> 5;
    int g = lane >> 2, t4 = lane & 3;
    int mt = wid & 3, half = wid >> 2;
    int r0 = blockIdx.x * 64, m0 = mt * 16;
    float acc[16][4];
#pragma unroll
    for (int n = 0; n < 16; n++) { acc[n][0] = acc[n][1] = acc[n][2] = acc[n][3] = 0.f; }

    for (int k0 = 0; k0 < HID; k0 += 16) {
        {
            int i = t;
            int row = i >> 2, c4 = (i & 3) * 4;
            int gr = min(r0 + row, N_NODES - 1);
            *(uint4*)&As[row * 20 + c4] =
                tf32c4(*(const float4*)(fin + (size_t)gr * HID + k0 + c4));
        }
        for (int i = t; i < 1024; i += 256) {
            int row = i >> 6, c4 = (i & 63) * 4;
            const float* srcp = (c4 < 128) ? (wv + (k0 + row) * HID + c4)
                                           : (wt + (k0 + row) * HID + (c4 - 128));
            *(uint4*)&Bs[row * 264 + c4] = tf32c4(*(const float4*)srcp);
        }
        __syncthreads();
#pragma unroll
        for (int ks = 0; ks < 2; ks++) {
            int ar = (m0 + g) * 20 + ks * 8 + t4;
            uint32_t a0 = As[ar], a1 = As[ar + 160], a2 = As[ar + 4], a3 = As[ar + 164];
            const uint32_t* bp = &Bs[(ks * 8 + t4) * 264 + half * 128];
#pragma unroll
            for (int nt = 0; nt < 16; nt++)
                mma8(acc[nt], a0, a1, a2, a3, bp[nt * 8 + g], bp[1056 + nt * 8 + g]);
        }
        __syncthreads();
    }

    const float* bias = half ? bt : bv;
    float* o = half ? txt : vis;
    int rA = r0 + m0 + g, rB = rA + 8;
#pragma unroll
    for (int nt = 0; nt < 16; nt++) {
        int cn = nt * 8 + t4 * 2;
        float b0 = bias[cn], b1 = bias[cn + 1];
        if (rA < N_NODES)
            *(float2*)&o[(size_t)rA * HID + cn] =
                make_float2(fmaxf(acc[nt][0] + b0, 0.f), fmaxf(acc[nt][1] + b1, 0.f));
        if (rB < N_NODES)
            *(float2*)&o[(size_t)rB * HID + cn] =
                make_float2(fmaxf(acc[nt][2] + b0, 0.f), fmaxf(acc[nt][3] + b1, 0.f));
    }
}

// ---------------- launcher ----------------
extern "C" void kernel_launch(void* const* d_in, const int* in_sizes, int n_in,
                              void* d_out, int out_size) {
    const float* x       = (const float*)d_in[0];
    const int*   ei      = (const int*)  d_in[1];
    const float* u       = (const float*)d_in[2];
    const float* w_feat  = (const float*)d_in[3];
    const float* b_feat  = (const float*)d_in[4];
    const float* w_hyper = (const float*)d_in[5];
    const float* w_vis   = (const float*)d_in[6];
    const float* b_vis   = (const float*)d_in[7];
    const float* w_txt   = (const float*)d_in[8];
    const float* b_txt   = (const float*)d_in[9];

    float* out  = (float*)d_out;
    float* outF = out;
    float* outV = out + (size_t)N_NODES * HID;
    float* outT = out + (size_t)2 * N_NODES * HID;

    const int* src = ei;
    const int* dst = ei + N_EDGES;

    int nb = (N_NODES + 1023) / 1024;         // 49
    int g128 = (N_NODES + 127) / 128;         // 391
    int g64  = (N_NODES + 63) / 64;           // 782

    k_zero <<<(N_NODES + 255) / 256, 256>>>();
    k_deg  <<<(N_EDGES + 255) / 256, 256>>>(dst);
    k_scan1<<<nb, 1024>>>();
    k_scan2<<<1, 64>>>(nb);
    k_scan3<<<nb, 1024>>>();
    k_dinv <<<(N_NODES + 255) / 256, 256>>>();
    k_fill <<<(N_EDGES + 255) / 256, 256>>>(src, dst);

    k_gemm1<<<g128, 256>>>(x, w_feat, b_feat);

    k_prop<<<(N_NODES + 3) / 4, 128>>>(0);
    k_prop<<<(N_NODES + 3) / 4, 128>>>(1);
    k_prop<<<(N_NODES + 3) / 4, 128>>>(2);

    k_hyp<<<g128, 256>>>(w_hyper, u);

    k_lat<<<LATB, 512>>>();
    k_latred<<<(HYP * HID + 1023) / 1024, 1024>>>();

    k_final<<<g128, 256>>>(outF);
    k_out  <<<g64, 256>>>(outF, w_vis, b_vis, w_txt, b_txt, outV, outT);
}